// round 13
// baseline (speedup 1.0000x reference)
#include <cuda_runtime.h>
#include <math.h>

#define BB 32
#define SS 4096
#define HH 1024
#define NCHUNK 32
#define CHUNK (SS / NCHUNK)            // 128 rows per tile
#define NTILES (NCHUNK * BB)           // 1024 work tiles
#define PERSIST 304                    // 2 CTAs/SM x 152 SMs
#define NEG_BIG -1.0e9f

// ---- scratch (no allocations allowed) ----
__device__ float g_qp[4 * BB * HH];               // split-K(4) projected-query partials
__device__ float g_part_m[BB * NCHUNK];           // per-chunk running max
__device__ float g_part_l[BB * NCHUNK];           // per-chunk exp-sum
__device__ float g_part_acc[BB * NCHUNK * HH];    // per-chunk unnormalized context (4MB)
__device__ float g_Mfin[BB];                      // global max per batch
__device__ float g_invL[BB];                      // 1/denominator per batch
__device__ unsigned int g_ctr;                    // persistent work counter

// ============================================================
// Kernel A: split-K(4) projection with SMEM-STAGED Q.
// grid (HH/16, 4, 4) = 1024 CTAs, 128 threads.
// Block (0,0,0) also resets the flash work counter (stream
// order guarantees this lands before flash launches).
// ============================================================
__global__ void __launch_bounds__(128) proj_kernel(
    const float* __restrict__ query, const float* __restrict__ W)
{
    __shared__ float4 sq2[8 * 64];     // 8 batches x 256 floats (k-quarter)
    const int tid = threadIdx.x;

    if (blockIdx.x == 0 && blockIdx.y == 0 && blockIdx.z == 0 && tid == 0)
        g_ctr = 0u;

    const int w = tid >> 5, lane = tid & 31;
    const int o0 = blockIdx.x * 16;
    const int b0 = blockIdx.y * 8;
    const int z = blockIdx.z;                      // k-quarter
    const int h0 = z * (HH / 4);                   // 0,256,512,768

    for (int i = tid; i < 8 * 64; i += 128) {
        const int bb = i >> 6, col = i & 63;
        sq2[i] = ((const float4*)(query + (size_t)(b0 + bb) * HH + h0))[col];
    }
    __syncthreads();

    float4 wv[4][2];
    #pragma unroll
    for (int r = 0; r < 4; r++) {
        const float4* wrow = (const float4*)(W + (size_t)(o0 + w * 4 + r) * HH + h0);
        wv[r][0] = __ldg(wrow + lane);
        wv[r][1] = __ldg(wrow + 32 + lane);
    }

    #pragma unroll
    for (int r = 0; r < 4; r++) {
        float p[8];
        #pragma unroll
        for (int bb = 0; bb < 8; bb++) {
            const float4 q0 = sq2[bb * 64 + lane];
            const float4 q1 = sq2[bb * 64 + 32 + lane];
            p[bb] = wv[r][0].x * q0.x + wv[r][0].y * q0.y
                  + wv[r][0].z * q0.z + wv[r][0].w * q0.w
                  + wv[r][1].x * q1.x + wv[r][1].y * q1.y
                  + wv[r][1].z * q1.z + wv[r][1].w * q1.w;
        }
        #pragma unroll
        for (int off = 16; off > 0; off >>= 1) {
            #pragma unroll
            for (int bb = 0; bb < 8; bb++)
                p[bb] += __shfl_xor_sync(0xffffffffu, p[bb], off);
        }
        if (lane == 0) {
            float* dst = g_qp + (size_t)z * BB * HH;
            #pragma unroll
            for (int bb = 0; bb < 8; bb++)
                dst[(size_t)(b0 + bb) * HH + (o0 + w * 4 + r)] = p[bb];
        }
    }
}

// ============================================================
// Kernel B: PERSISTENT mask-skip flash (compaction + prefetch).
// [UNCHANGED from R12 — ~49-50us measured via ledger]
// ============================================================
__global__ void __launch_bounds__(256) flash_kernel(
    const float* __restrict__ keys,
    const int* __restrict__ mask,
    float* __restrict__ scores_out)
{
    const int tid = threadIdx.x, w = tid >> 5, lane = tid & 31;

    __shared__ float4 sq[HH / 4];          // 4KB projected query
    __shared__ float  s_m[8], s_l[8];
    __shared__ float4 s_acc[8][256];       // 32KB warp partial contexts
    __shared__ int    s_idx[CHUNK];
    __shared__ int    s_n;
    __shared__ int    s_tile;

    while (true) {
        if (tid == 0) s_tile = (int)atomicAdd(&g_ctr, 1u);
        __syncthreads();                   // also fences prev-tile smem reads
        const int t = s_tile;
        if (t >= NTILES) break;

        const int chunk = t & (NCHUNK - 1);
        const int b = t >> 5;
        const int s0 = chunk * CHUNK;
        const int* mrow = mask + (size_t)b * SS;

        // q = sum of split-K(4) partials
        {
            const size_t base = (size_t)b * (HH / 4);
            const float4* q0 = (const float4*)(g_qp) + base;
            const float4* q1 = (const float4*)(g_qp + (size_t)BB * HH) + base;
            const float4* q2 = (const float4*)(g_qp + (size_t)2 * BB * HH) + base;
            const float4* q3 = (const float4*)(g_qp + (size_t)3 * BB * HH) + base;
            for (int i = tid; i < HH / 4; i += 256) {
                float4 a = q0[i], c2 = q1[i], d = q2[i], e2 = q3[i];
                sq[i] = make_float4(a.x + c2.x + d.x + e2.x, a.y + c2.y + d.y + e2.y,
                                    a.z + c2.z + d.z + e2.z, a.w + c2.w + d.w + e2.w);
            }
        }

        // ---- compaction: warp 0 builds unmasked index list ----
        if (w == 0) {
            int base = 0;
            #pragma unroll
            for (int g = 0; g < CHUNK / 32; g++) {
                const int s = s0 + g * 32 + lane;
                const int mk = mrow[s];
                const unsigned bal = __ballot_sync(0xffffffffu, mk == 0);
                if (mk != 0) scores_out[(size_t)b * SS + s] = NEG_BIG;
                const int pos = base + __popc(bal & ((1u << lane) - 1u));
                if (mk == 0) s_idx[pos] = g * 32 + lane;
                base += __popc(bal);
            }
            if (lane == 0) s_n = base;
        }
        __syncthreads();

        const int n = s_n;
        const int pidx = b * NCHUNK + chunk;

        if (n == 0) {
            ((float4*)(g_part_acc + (size_t)pidx * HH))[tid] =
                make_float4(0.f, 0.f, 0.f, 0.f);
            if (tid == 0) {
                g_part_m[pidx] = NEG_BIG;
                g_part_l[pidx] = (float)CHUNK;
            }
            continue;
        }

        float4 acc[8];
        #pragma unroll
        for (int j = 0; j < 8; j++) acc[j] = make_float4(0.f, 0.f, 0.f, 0.f);
        float m = -INFINITY, l = 0.f;

        const float* kb = keys + (size_t)b * SS * HH + (size_t)s0 * HH;

        float4 kv[8], pf[4];
        int i = w;
        if (i < n) {
            const float4* kp = (const float4*)(kb + (size_t)s_idx[i] * HH);
            #pragma unroll
            for (int j = 0; j < 8; j++) kv[j] = __ldcs(kp + j * 32 + lane);
        }

        while (i < n) {
            float pa = 0.f, pb = 0.f;
            #pragma unroll
            for (int j = 0; j < 8; j += 2) {
                float4 qe = sq[j * 32 + lane], qo = sq[(j + 1) * 32 + lane];
                pa += kv[j].x * qe.x + kv[j].y * qe.y + kv[j].z * qe.z + kv[j].w * qe.w;
                pb += kv[j+1].x * qo.x + kv[j+1].y * qo.y + kv[j+1].z * qo.z + kv[j+1].w * qo.w;
            }
            float p = pa + pb;

            const int inext = i + 8;
            const float4* kpn = nullptr;
            if (inext < n) {
                kpn = (const float4*)(kb + (size_t)s_idx[inext] * HH);
                #pragma unroll
                for (int j = 0; j < 4; j++) pf[j] = __ldcs(kpn + j * 32 + lane);
            }

            #pragma unroll
            for (int off = 16; off > 0; off >>= 1)
                p += __shfl_xor_sync(0xffffffffu, p, off);

            const int s = s0 + s_idx[i];
            if (lane == 0) scores_out[(size_t)b * SS + s] = p;

            const float mn = fmaxf(m, p);
            const float c  = __expf(m - mn);
            const float e  = __expf(p - mn);
            l = l * c + e;
            #pragma unroll
            for (int j = 0; j < 8; j++) {
                acc[j].x = acc[j].x * c + e * kv[j].x;
                acc[j].y = acc[j].y * c + e * kv[j].y;
                acc[j].z = acc[j].z * c + e * kv[j].z;
                acc[j].w = acc[j].w * c + e * kv[j].w;
            }
            m = mn;

            if (inext < n) {
                #pragma unroll
                for (int j = 0; j < 4; j++) kv[j] = pf[j];
                #pragma unroll
                for (int j = 4; j < 8; j++) kv[j] = __ldcs(kpn + j * 32 + lane);
            }
            i = inext;
        }

        // ---- combine 8 warps ----
        if (lane == 0) { s_m[w] = m; s_l[w] = l; }
        #pragma unroll
        for (int j = 0; j < 8; j++) s_acc[w][j * 32 + lane] = acc[j];
        __syncthreads();

        float M = s_m[0];
        #pragma unroll
        for (int i2 = 1; i2 < 8; i2++) M = fmaxf(M, s_m[i2]);
        float ew[8], L = 0.f;
        #pragma unroll
        for (int i2 = 0; i2 < 8; i2++) {
            ew[i2] = (s_m[i2] == -INFINITY) ? 0.f : __expf(s_m[i2] - M);
            L += ew[i2] * s_l[i2];
        }

        float4 cacc = make_float4(0.f, 0.f, 0.f, 0.f);
        #pragma unroll
        for (int i2 = 0; i2 < 8; i2++) {
            float4 v = s_acc[i2][tid];
            cacc.x += ew[i2] * v.x; cacc.y += ew[i2] * v.y;
            cacc.z += ew[i2] * v.z; cacc.w += ew[i2] * v.w;
        }
        ((float4*)(g_part_acc + (size_t)pidx * HH))[tid] = cacc;
        if (tid == 0) { g_part_m[pidx] = M; g_part_l[pidx] = L; }
    }
}

// ============================================================
// Kernel C1: per-batch softmax stats. 32 blocks x 32 threads;
// lane c owns chunk c (NCHUNK == 32). Shfl reductions.
// All-masked chunk: m=-1e9 -> exp(m-M)*l underflows to 0,
// identical to the old finalize arithmetic.
// ============================================================
__global__ void __launch_bounds__(32) stats_kernel()
{
    const int b = blockIdx.x, lane = threadIdx.x;
    const float mv = g_part_m[b * NCHUNK + lane];
    const float lv = g_part_l[b * NCHUNK + lane];

    float M = mv;
    #pragma unroll
    for (int off = 16; off > 0; off >>= 1)
        M = fmaxf(M, __shfl_xor_sync(0xffffffffu, M, off));

    float contrib = __expf(mv - M) * lv;
    #pragma unroll
    for (int off = 16; off > 0; off >>= 1)
        contrib += __shfl_xor_sync(0xffffffffu, contrib, off);

    if (lane == 0) { g_Mfin[b] = M; g_invL[b] = 1.f / contrib; }
}

// ============================================================
// Kernel C2: finalize. grid (BB, 5) x 256 threads, every
// thread exactly ONE float4. Parts 0-3: weight slices of 1024
// floats (vectorized in-place normalize). Part 4: context.
// ============================================================
__global__ void __launch_bounds__(256) finalize_kernel(float* __restrict__ out)
{
    const int b = blockIdx.x, part = blockIdx.y, tid = threadIdx.x;
    const float M = g_Mfin[b];
    const float invL = g_invL[b];

    if (part == 4) {
        // context [B,1,H]
        float4 ctx = make_float4(0.f, 0.f, 0.f, 0.f);
        #pragma unroll 4
        for (int c = 0; c < NCHUNK; c++) {
            const float ew = __expf(g_part_m[b * NCHUNK + c] - M);
            float4 v = ((const float4*)(g_part_acc + (size_t)(b * NCHUNK + c) * HH))[tid];
            ctx.x += ew * v.x; ctx.y += ew * v.y;
            ctx.z += ew * v.z; ctx.w += ew * v.w;
        }
        ctx.x *= invL; ctx.y *= invL; ctx.z *= invL; ctx.w *= invL;
        ((float4*)(out + (size_t)b * HH))[tid] = ctx;
    } else {
        // weights [B,1,S]: slice of 1024 floats = 256 float4
        float4* wout = (float4*)(out + (size_t)BB * HH + (size_t)b * SS) + part * 256;
        float4 v = wout[tid];
        v.x = __expf(v.x - M) * invL;
        v.y = __expf(v.y - M) * invL;
        v.z = __expf(v.z - M) * invL;
        v.w = __expf(v.w - M) * invL;
        wout[tid] = v;
    }
}

extern "C" void kernel_launch(void* const* d_in, const int* in_sizes, int n_in,
                              void* d_out, int out_size)
{
    const float* query = nullptr;
    const float* keys  = nullptr;
    const int*   mask  = nullptr;
    const float* W     = nullptr;
    for (int i = 0; i < n_in; i++) {
        switch (in_sizes[i]) {
            case BB * HH:        query = (const float*)d_in[i]; break;  // 32768
            case BB * SS * HH:   keys  = (const float*)d_in[i]; break;  // 134217728
            case BB * SS:        mask  = (const int*)d_in[i];   break;  // 131072
            case HH * HH:        W     = (const float*)d_in[i]; break;  // 1048576
            default: break;
        }
    }
    float* out = (float*)d_out;

    proj_kernel<<<dim3(HH / 16, 4, 4), 128>>>(query, W);
    flash_kernel<<<PERSIST, 256>>>(keys, mask, out + (size_t)BB * HH);
    stats_kernel<<<BB, 32>>>();
    finalize_kernel<<<dim3(BB, 5), 256>>>(out);
}

// round 14
// speedup vs baseline: 1.0427x; 1.0427x over previous
#include <cuda_runtime.h>
#include <math.h>

#define BB 32
#define SS 4096
#define HH 1024
#define NCHUNK 32
#define CHUNK (SS / NCHUNK)            // 128 rows per tile
#define NTILES (NCHUNK * BB)           // 1024 work tiles
#define PERSIST 304                    // 2 CTAs/SM
#define NEG_BIG -1.0e9f

// ---- scratch (no allocations allowed) ----
__device__ float g_qp[4 * BB * HH];               // split-K(4) projected-query partials
__device__ float g_part_m[BB * NCHUNK];           // per-chunk running max
__device__ float g_part_l[BB * NCHUNK];           // per-chunk exp-sum
__device__ float g_part_acc[BB * NCHUNK * HH];    // per-chunk unnormalized context (4MB)
__device__ unsigned int g_ctr;                    // persistent work counter

// ============================================================
// Kernel A: split-K(4) projection with SMEM-STAGED Q.
// [UNCHANGED from R13] grid (HH/16, 4, 4), 128 threads.
// Block (0,0,0) resets the flash work counter.
// ============================================================
__global__ void __launch_bounds__(128) proj_kernel(
    const float* __restrict__ query, const float* __restrict__ W)
{
    __shared__ float4 sq2[8 * 64];     // 8 batches x 256 floats (k-quarter)
    const int tid = threadIdx.x;

    if (blockIdx.x == 0 && blockIdx.y == 0 && blockIdx.z == 0 && tid == 0)
        g_ctr = 0u;

    const int w = tid >> 5, lane = tid & 31;
    const int o0 = blockIdx.x * 16;
    const int b0 = blockIdx.y * 8;
    const int z = blockIdx.z;                      // k-quarter
    const int h0 = z * (HH / 4);                   // 0,256,512,768

    for (int i = tid; i < 8 * 64; i += 128) {
        const int bb = i >> 6, col = i & 63;
        sq2[i] = ((const float4*)(query + (size_t)(b0 + bb) * HH + h0))[col];
    }
    __syncthreads();

    float4 wv[4][2];
    #pragma unroll
    for (int r = 0; r < 4; r++) {
        const float4* wrow = (const float4*)(W + (size_t)(o0 + w * 4 + r) * HH + h0);
        wv[r][0] = __ldg(wrow + lane);
        wv[r][1] = __ldg(wrow + 32 + lane);
    }

    #pragma unroll
    for (int r = 0; r < 4; r++) {
        float p[8];
        #pragma unroll
        for (int bb = 0; bb < 8; bb++) {
            const float4 q0 = sq2[bb * 64 + lane];
            const float4 q1 = sq2[bb * 64 + 32 + lane];
            p[bb] = wv[r][0].x * q0.x + wv[r][0].y * q0.y
                  + wv[r][0].z * q0.z + wv[r][0].w * q0.w
                  + wv[r][1].x * q1.x + wv[r][1].y * q1.y
                  + wv[r][1].z * q1.z + wv[r][1].w * q1.w;
        }
        #pragma unroll
        for (int off = 16; off > 0; off >>= 1) {
            #pragma unroll
            for (int bb = 0; bb < 8; bb++)
                p[bb] += __shfl_xor_sync(0xffffffffu, p[bb], off);
        }
        if (lane == 0) {
            float* dst = g_qp + (size_t)z * BB * HH;
            #pragma unroll
            for (int bb = 0; bb < 8; bb++)
                dst[(size_t)(b0 + bb) * HH + (o0 + w * 4 + r)] = p[bb];
        }
    }
}

// ============================================================
// Kernel B: PERSISTENT mask-skip flash (compaction + prefetch).
// [UNCHANGED from R12/R13 — ~49us]
// ============================================================
__global__ void __launch_bounds__(256) flash_kernel(
    const float* __restrict__ keys,
    const int* __restrict__ mask,
    float* __restrict__ scores_out)
{
    const int tid = threadIdx.x, w = tid >> 5, lane = tid & 31;

    __shared__ float4 sq[HH / 4];          // 4KB projected query
    __shared__ float  s_m[8], s_l[8];
    __shared__ float4 s_acc[8][256];       // 32KB warp partial contexts
    __shared__ int    s_idx[CHUNK];
    __shared__ int    s_n;
    __shared__ int    s_tile;

    while (true) {
        if (tid == 0) s_tile = (int)atomicAdd(&g_ctr, 1u);
        __syncthreads();                   // also fences prev-tile smem reads
        const int t = s_tile;
        if (t >= NTILES) break;

        const int chunk = t & (NCHUNK - 1);
        const int b = t >> 5;
        const int s0 = chunk * CHUNK;
        const int* mrow = mask + (size_t)b * SS;

        // q = sum of split-K(4) partials
        {
            const size_t base = (size_t)b * (HH / 4);
            const float4* q0 = (const float4*)(g_qp) + base;
            const float4* q1 = (const float4*)(g_qp + (size_t)BB * HH) + base;
            const float4* q2 = (const float4*)(g_qp + (size_t)2 * BB * HH) + base;
            const float4* q3 = (const float4*)(g_qp + (size_t)3 * BB * HH) + base;
            for (int i = tid; i < HH / 4; i += 256) {
                float4 a = q0[i], c2 = q1[i], d = q2[i], e2 = q3[i];
                sq[i] = make_float4(a.x + c2.x + d.x + e2.x, a.y + c2.y + d.y + e2.y,
                                    a.z + c2.z + d.z + e2.z, a.w + c2.w + d.w + e2.w);
            }
        }

        // ---- compaction: warp 0 builds unmasked index list ----
        if (w == 0) {
            int base = 0;
            #pragma unroll
            for (int g = 0; g < CHUNK / 32; g++) {
                const int s = s0 + g * 32 + lane;
                const int mk = mrow[s];
                const unsigned bal = __ballot_sync(0xffffffffu, mk == 0);
                if (mk != 0) scores_out[(size_t)b * SS + s] = NEG_BIG;
                const int pos = base + __popc(bal & ((1u << lane) - 1u));
                if (mk == 0) s_idx[pos] = g * 32 + lane;
                base += __popc(bal);
            }
            if (lane == 0) s_n = base;
        }
        __syncthreads();

        const int n = s_n;
        const int pidx = b * NCHUNK + chunk;

        if (n == 0) {
            ((float4*)(g_part_acc + (size_t)pidx * HH))[tid] =
                make_float4(0.f, 0.f, 0.f, 0.f);
            if (tid == 0) {
                g_part_m[pidx] = NEG_BIG;
                g_part_l[pidx] = (float)CHUNK;
            }
            continue;
        }

        float4 acc[8];
        #pragma unroll
        for (int j = 0; j < 8; j++) acc[j] = make_float4(0.f, 0.f, 0.f, 0.f);
        float m = -INFINITY, l = 0.f;

        const float* kb = keys + (size_t)b * SS * HH + (size_t)s0 * HH;

        float4 kv[8], pf[4];
        int i = w;
        if (i < n) {
            const float4* kp = (const float4*)(kb + (size_t)s_idx[i] * HH);
            #pragma unroll
            for (int j = 0; j < 8; j++) kv[j] = __ldcs(kp + j * 32 + lane);
        }

        while (i < n) {
            float pa = 0.f, pb = 0.f;
            #pragma unroll
            for (int j = 0; j < 8; j += 2) {
                float4 qe = sq[j * 32 + lane], qo = sq[(j + 1) * 32 + lane];
                pa += kv[j].x * qe.x + kv[j].y * qe.y + kv[j].z * qe.z + kv[j].w * qe.w;
                pb += kv[j+1].x * qo.x + kv[j+1].y * qo.y + kv[j+1].z * qo.z + kv[j+1].w * qo.w;
            }
            float p = pa + pb;

            const int inext = i + 8;
            const float4* kpn = nullptr;
            if (inext < n) {
                kpn = (const float4*)(kb + (size_t)s_idx[inext] * HH);
                #pragma unroll
                for (int j = 0; j < 4; j++) pf[j] = __ldcs(kpn + j * 32 + lane);
            }

            #pragma unroll
            for (int off = 16; off > 0; off >>= 1)
                p += __shfl_xor_sync(0xffffffffu, p, off);

            const int s = s0 + s_idx[i];
            if (lane == 0) scores_out[(size_t)b * SS + s] = p;

            const float mn = fmaxf(m, p);
            const float c  = __expf(m - mn);
            const float e  = __expf(p - mn);
            l = l * c + e;
            #pragma unroll
            for (int j = 0; j < 8; j++) {
                acc[j].x = acc[j].x * c + e * kv[j].x;
                acc[j].y = acc[j].y * c + e * kv[j].y;
                acc[j].z = acc[j].z * c + e * kv[j].z;
                acc[j].w = acc[j].w * c + e * kv[j].w;
            }
            m = mn;

            if (inext < n) {
                #pragma unroll
                for (int j = 0; j < 4; j++) kv[j] = pf[j];
                #pragma unroll
                for (int j = 4; j < 8; j++) kv[j] = __ldcs(kpn + j * 32 + lane);
            }
            i = inext;
        }

        // ---- combine 8 warps ----
        if (lane == 0) { s_m[w] = m; s_l[w] = l; }
        #pragma unroll
        for (int j = 0; j < 8; j++) s_acc[w][j * 32 + lane] = acc[j];
        __syncthreads();

        float M = s_m[0];
        #pragma unroll
        for (int i2 = 1; i2 < 8; i2++) M = fmaxf(M, s_m[i2]);
        float ew[8], L = 0.f;
        #pragma unroll
        for (int i2 = 0; i2 < 8; i2++) {
            ew[i2] = (s_m[i2] == -INFINITY) ? 0.f : __expf(s_m[i2] - M);
            L += ew[i2] * s_l[i2];
        }

        float4 cacc = make_float4(0.f, 0.f, 0.f, 0.f);
        #pragma unroll
        for (int i2 = 0; i2 < 8; i2++) {
            float4 v = s_acc[i2][tid];
            cacc.x += ew[i2] * v.x; cacc.y += ew[i2] * v.y;
            cacc.z += ew[i2] * v.z; cacc.w += ew[i2] * v.w;
        }
        ((float4*)(g_part_acc + (size_t)pidx * HH))[tid] = cacc;
        if (tid == 0) { g_part_m[pidx] = M; g_part_l[pidx] = L; }
    }
}

// ============================================================
// Kernel C: finalize (stats folded back in, deep-MLP streaming).
// grid (BB, 3) x 256 threads.
// Every block derives M/invL locally (64 broadcast loads, L2-hot
// after block 0). Parts 0-1: weight halves, 2 float4/thread in
// flight. Part 2: context; partials read in 2 register batches
// of 16 float4 (MLP=16) to hide the 577-cyc DRAM latency.
// ============================================================
__global__ void __launch_bounds__(256) finalize_kernel(float* __restrict__ out)
{
    const int b = blockIdx.x, part = blockIdx.y, tid = threadIdx.x;

    // per-block stats (independent loads, fully unrolled)
    float mv[NCHUNK];
    #pragma unroll
    for (int c = 0; c < NCHUNK; c++) mv[c] = g_part_m[b * NCHUNK + c];
    float M = mv[0];
    #pragma unroll
    for (int c = 1; c < NCHUNK; c++) M = fmaxf(M, mv[c]);
    float L = 0.f;
    #pragma unroll
    for (int c = 0; c < NCHUNK; c++)
        L += __expf(mv[c] - M) * g_part_l[b * NCHUNK + c];
    const float invL = 1.f / L;

    if (part == 2) {
        // context [B,1,H]: 32 partials in 2 batches of 16 (MLP=16)
        float ew[NCHUNK];
        #pragma unroll
        for (int c = 0; c < NCHUNK; c++) ew[c] = __expf(mv[c] - M);

        const float4* pacc = (const float4*)(g_part_acc) + (size_t)b * NCHUNK * 256 + tid;
        float4 ctx = make_float4(0.f, 0.f, 0.f, 0.f);
        #pragma unroll
        for (int h = 0; h < 2; h++) {
            float4 v[16];
            #pragma unroll
            for (int c = 0; c < 16; c++) v[c] = __ldg(pacc + (size_t)(h * 16 + c) * 256);
            #pragma unroll
            for (int c = 0; c < 16; c++) {
                const float e = ew[h * 16 + c];
                ctx.x += e * v[c].x; ctx.y += e * v[c].y;
                ctx.z += e * v[c].z; ctx.w += e * v[c].w;
            }
        }
        ctx.x *= invL; ctx.y *= invL; ctx.z *= invL; ctx.w *= invL;
        ((float4*)(out + (size_t)b * HH))[tid] = ctx;
    } else {
        // weights [B,1,S]: half-slice of 2048 floats, 2 float4/thread in flight
        float4* wout = (float4*)(out + (size_t)BB * HH + (size_t)b * SS) + part * 512 + tid;
        float4 v0 = wout[0];
        float4 v1 = wout[256];
        v0.x = __expf(v0.x - M) * invL; v0.y = __expf(v0.y - M) * invL;
        v0.z = __expf(v0.z - M) * invL; v0.w = __expf(v0.w - M) * invL;
        v1.x = __expf(v1.x - M) * invL; v1.y = __expf(v1.y - M) * invL;
        v1.z = __expf(v1.z - M) * invL; v1.w = __expf(v1.w - M) * invL;
        wout[0] = v0;
        wout[256] = v1;
    }
}

extern "C" void kernel_launch(void* const* d_in, const int* in_sizes, int n_in,
                              void* d_out, int out_size)
{
    const float* query = nullptr;
    const float* keys  = nullptr;
    const int*   mask  = nullptr;
    const float* W     = nullptr;
    for (int i = 0; i < n_in; i++) {
        switch (in_sizes[i]) {
            case BB * HH:        query = (const float*)d_in[i]; break;  // 32768
            case BB * SS * HH:   keys  = (const float*)d_in[i]; break;  // 134217728
            case BB * SS:        mask  = (const int*)d_in[i];   break;  // 131072
            case HH * HH:        W     = (const float*)d_in[i]; break;  // 1048576
            default: break;
        }
    }
    float* out = (float*)d_out;

    proj_kernel<<<dim3(HH / 16, 4, 4), 128>>>(query, W);
    flash_kernel<<<PERSIST, 256>>>(keys, mask, out + (size_t)BB * HH);
    finalize_kernel<<<dim3(BB, 3), 256>>>(out);
}